// round 1
// baseline (speedup 1.0000x reference)
#include <cuda_runtime.h>
#include <cuda_bf16.h>

// Problem constants (fixed by the dataset)
#define NN 50000      // nodes
#define EE 800000     // edges
#define DD 512        // input feature dim
#define FF 256        // output feature dim

// ---------------- device scratch (allocation-free rule: __device__ globals) ----
__device__ float g_support[2 * (size_t)NN * FF];   // 102.4 MB: X@W for both branches
__device__ int   g_counts[NN + 1];
__device__ int   g_offsets[NN + 1];
__device__ int   g_cursor[NN];
__device__ int   g_ecol[EE];
__device__ float g_eval[EE];

// ---------------- GEMM: S[b] = X_b @ W,  X:[M,512] row-major, W:[512,256] row-major
// 128x128 tile, BK=16, 256 threads, 8x8 micro-tile split as (2x4)x(2x4) for
// conflict-free float4 shared loads.
__global__ __launch_bounds__(256, 2)
void gemm_kernel(const float* __restrict__ A0, const float* __restrict__ A1,
                 const float* __restrict__ B, int M)
{
    const int K = DD, Nn = FF;
    const float* A = blockIdx.z ? A1 : A0;
    float* S = g_support + (size_t)blockIdx.z * M * Nn;

    __shared__ float As[16][128];
    __shared__ float Bs[16][128];

    const int tid  = threadIdx.x;
    const int brow = blockIdx.x * 128;
    const int bcol = blockIdx.y * 128;
    const int ty   = tid / 16;   // 0..15
    const int tx   = tid % 16;   // 0..15

    float acc[8][8];
#pragma unroll
    for (int i = 0; i < 8; i++)
#pragma unroll
        for (int j = 0; j < 8; j++) acc[i][j] = 0.f;

    for (int k0 = 0; k0 < K; k0 += 16) {
        // load A tile: 128 rows x 16 cols (guard rows)
#pragma unroll
        for (int i = 0; i < 2; i++) {
            int r  = tid / 4 + i * 64;          // 0..127
            int c4 = (tid % 4) * 4;             // 0,4,8,12
            float4 v = make_float4(0.f, 0.f, 0.f, 0.f);
            int gr = brow + r;
            if (gr < M) v = *(const float4*)&A[(size_t)gr * K + k0 + c4];
            As[c4 + 0][r] = v.x;
            As[c4 + 1][r] = v.y;
            As[c4 + 2][r] = v.z;
            As[c4 + 3][r] = v.w;
        }
        // load B tile: 16 rows x 128 cols (always in-range: K,N multiples)
#pragma unroll
        for (int i = 0; i < 2; i++) {
            int r  = tid / 32 + i * 8;          // 0..15
            int c4 = (tid % 32) * 4;            // 0..124
            *(float4*)&Bs[r][c4] = *(const float4*)&B[(size_t)(k0 + r) * Nn + bcol + c4];
        }
        __syncthreads();

#pragma unroll
        for (int kk = 0; kk < 16; kk++) {
            float a[8], b[8];
            *(float4*)&a[0] = *(const float4*)&As[kk][ty * 4];
            *(float4*)&a[4] = *(const float4*)&As[kk][64 + ty * 4];
            *(float4*)&b[0] = *(const float4*)&Bs[kk][tx * 4];
            *(float4*)&b[4] = *(const float4*)&Bs[kk][64 + tx * 4];
#pragma unroll
            for (int i = 0; i < 8; i++)
#pragma unroll
                for (int j = 0; j < 8; j++)
                    acc[i][j] = fmaf(a[i], b[j], acc[i][j]);
        }
        __syncthreads();
    }

    // store: rows (i/4)*64 + ty*4 + i%4, cols (j/4)*64 + tx*4 + j%4
#pragma unroll
    for (int i = 0; i < 8; i++) {
        int r = brow + (i / 4) * 64 + ty * 4 + (i % 4);
        if (r < M) {
            float4 v0 = make_float4(acc[i][0], acc[i][1], acc[i][2], acc[i][3]);
            float4 v1 = make_float4(acc[i][4], acc[i][5], acc[i][6], acc[i][7]);
            *(float4*)&S[(size_t)r * Nn + bcol + tx * 4]      = v0;
            *(float4*)&S[(size_t)r * Nn + bcol + 64 + tx * 4] = v1;
        }
    }
}

// ---------------- CSR build ----------------
__global__ void zero_counts_kernel(int n)
{
    int i = blockIdx.x * blockDim.x + threadIdx.x;
    if (i <= n) g_counts[i] = 0;
}

__global__ void hist_kernel(const int* __restrict__ row, int E)
{
    int e = blockIdx.x * blockDim.x + threadIdx.x;
    if (e < E) atomicAdd(&g_counts[row[e]], 1);
}

__global__ void scan_kernel(int n, int E)
{
    __shared__ int sdata[1024];
    int t = threadIdx.x;
    int chunk = (n + 1023) / 1024;
    int begin = t * chunk;
    int end   = begin + chunk;
    if (end > n) end = n;
    int s = 0;
    for (int i = begin; i < end; i++) s += g_counts[i];
    sdata[t] = s;
    __syncthreads();
    // Hillis-Steele inclusive scan
    for (int off = 1; off < 1024; off <<= 1) {
        int v = (t >= off) ? sdata[t - off] : 0;
        __syncthreads();
        sdata[t] += v;
        __syncthreads();
    }
    int run = sdata[t] - s;    // exclusive prefix at chunk start
    for (int i = begin; i < end; i++) {
        g_offsets[i] = run;
        g_cursor[i]  = run;
        run += g_counts[i];
    }
    if (t == 1023) g_offsets[n] = E;
}

__global__ void scatter_kernel(const int* __restrict__ row, const int* __restrict__ col,
                               const float* __restrict__ val, int E)
{
    int e = blockIdx.x * blockDim.x + threadIdx.x;
    if (e < E) {
        int r = row[e];
        int p = atomicAdd(&g_cursor[r], 1);
        g_ecol[p] = col[e];
        g_eval[p] = val[e];
    }
}

// ---------------- aggregation + bias + relu ----------------
// block = (row, branch), 256 threads = one feature each
__global__ __launch_bounds__(256)
void aggregate_kernel(const float* __restrict__ bias, float* __restrict__ out, int n)
{
    const int row = blockIdx.x;
    const int br  = blockIdx.y;
    const int f   = threadIdx.x;

    const float* __restrict__ S = g_support + (size_t)br * n * FF;
    int beg = g_offsets[row];
    int end = g_offsets[row + 1];

    __shared__ int   sc[64];
    __shared__ float sv[64];

    float acc = 0.f;
    for (int j0 = beg; j0 < end; j0 += 64) {
        int nb = end - j0;
        if (nb > 64) nb = 64;
        if (f < nb) {
            sc[f] = g_ecol[j0 + f];
            sv[f] = g_eval[j0 + f];
        }
        __syncthreads();
        for (int k = 0; k < nb; k++)
            acc = fmaf(sv[k], S[(size_t)sc[k] * FF + f], acc);
        __syncthreads();
    }

    float r = acc + bias[f];
    out[((size_t)br * n + row) * FF + f] = fmaxf(r, 0.f);
}

// ---------------- launch ----------------
extern "C" void kernel_launch(void* const* d_in, const int* in_sizes, int n_in,
                              void* d_out, int out_size)
{
    const float* feature_ori = (const float*)d_in[0];
    const float* feature_aug = (const float*)d_in[1];
    const int*   edge_row    = (const int*)d_in[2];
    const int*   edge_col    = (const int*)d_in[3];
    const float* edge_val    = (const float*)d_in[4];
    const float* weight      = (const float*)d_in[5];
    const float* bias        = (const float*)d_in[6];
    float*       out         = (float*)d_out;

    const int N = in_sizes[0] / DD;   // 50000
    const int E = in_sizes[2];        // 800000

    // 1) support = X @ W, both branches
    dim3 ggrid((N + 127) / 128, FF / 128, 2);
    gemm_kernel<<<ggrid, 256>>>(feature_ori, feature_aug, weight, N);

    // 2) CSR build
    zero_counts_kernel<<<(N + 256) / 256, 256>>>(N);
    hist_kernel<<<(E + 255) / 256, 256>>>(edge_row, E);
    scan_kernel<<<1, 1024>>>(N, E);
    scatter_kernel<<<(E + 255) / 256, 256>>>(edge_row, edge_col, edge_val, E);

    // 3) aggregate + bias + relu
    dim3 agrid(N, 2);
    aggregate_kernel<<<agrid, 256>>>(bias, out, N);
}

// round 3
// speedup vs baseline: 1.4715x; 1.4715x over previous
#include <cuda_runtime.h>
#include <cuda_bf16.h>
#include <cstdint>

#define NN 50000
#define EE 800000
#define DD 512
#define FF 256

// ---------------- device scratch ----------------
__device__ float         g_support[2 * (size_t)NN * FF];   // 102.4 MB
__device__ __nv_bfloat16 g_Bhi[FF * DD];                   // W^T hi, [256][512]
__device__ __nv_bfloat16 g_Blo[FF * DD];                   // W^T lo
__device__ int           g_counts[NN + 1];
__device__ int           g_offsets[NN + 1];
__device__ int           g_cursor[NN];
__device__ int           g_bsum[256];
__device__ int           g_bsum2[256];
__device__ int           g_ecol[EE];
__device__ float         g_eval[EE];

// ---------------- W prep: W[512][256] fp32 -> W^T hi/lo bf16 [256][512] ------
__global__ void prep_w_kernel(const float* __restrict__ W)
{
    int i = blockIdx.x * blockDim.x + threadIdx.x;
    if (i < DD * FF) {
        int k = i >> 8, n = i & 255;
        float w = W[i];
        __nv_bfloat16 h = __float2bfloat16(w);
        g_Bhi[n * DD + k] = h;
        g_Blo[n * DD + k] = __float2bfloat16(w - __bfloat162float(h));
    }
}

// ---------------- mma.sync bf16 GEMM (3-term hi/lo split) --------------------
// S[b] = X_b @ W.  Block tile 128x128, BK=32, 8 warps (4x2), warp tile 32x64.
#define BM 128
#define BN 128
#define BK 32
#define PADK 40   // smem k-stride in bf16 (80 bytes) -> conflict-free frag LDS

__device__ __forceinline__ void mma16816(float* c, const uint32_t* a, const uint32_t* b)
{
    asm volatile(
        "mma.sync.aligned.m16n8k16.row.col.f32.bf16.bf16.f32 "
        "{%0,%1,%2,%3}, {%4,%5,%6,%7}, {%8,%9}, {%0,%1,%2,%3};"
        : "+f"(c[0]), "+f"(c[1]), "+f"(c[2]), "+f"(c[3])
        : "r"(a[0]), "r"(a[1]), "r"(a[2]), "r"(a[3]), "r"(b[0]), "r"(b[1]));
}

__device__ __forceinline__ uint32_t pk2(__nv_bfloat16 a, __nv_bfloat16 b) {
    __nv_bfloat162 t; t.x = a; t.y = b;
    return *reinterpret_cast<uint32_t*>(&t);
}

__global__ __launch_bounds__(256, 1)
void gemm_mma_kernel(const float* __restrict__ A0, const float* __restrict__ A1, int M)
{
    __shared__ __nv_bfloat16 sAhi[BM * PADK];
    __shared__ __nv_bfloat16 sAlo[BM * PADK];
    __shared__ __nv_bfloat16 sBhi[BN * PADK];
    __shared__ __nv_bfloat16 sBlo[BN * PADK];

    const int tid  = threadIdx.x;
    const int lane = tid & 31;
    const int w    = tid >> 5;
    const int wm   = (w >> 1) * 32;       // warp m origin (0,32,64,96)
    const int wn   = (w & 1) * 64;        // warp n origin (0,64)
    const int g    = lane >> 2;           // 0..7
    const int t    = lane & 3;            // 0..3

    const int m0 = blockIdx.x * BM;
    const int n0 = blockIdx.y * BN;
    const float* __restrict__ A = blockIdx.z ? A1 : A0;
    float* __restrict__ S = g_support + (size_t)blockIdx.z * M * FF;

    float acc[2][8][4];
#pragma unroll
    for (int mi = 0; mi < 2; mi++)
#pragma unroll
        for (int ni = 0; ni < 8; ni++)
#pragma unroll
            for (int j = 0; j < 4; j++) acc[mi][ni][j] = 0.f;

    for (int kc = 0; kc < DD; kc += BK) {
        // ---- A tile: 128x32 fp32 -> hi/lo bf16, pad-40 layout ----
#pragma unroll
        for (int it = 0; it < 4; it++) {
            int f   = tid + it * 256;     // 0..1023 float4 slots
            int row = f >> 3;
            int k4  = (f & 7) * 4;
            float4 v = make_float4(0.f, 0.f, 0.f, 0.f);
            if (m0 + row < M)
                v = *(const float4*)&A[(size_t)(m0 + row) * DD + kc + k4];
            __nv_bfloat16 hx = __float2bfloat16(v.x), hy = __float2bfloat16(v.y);
            __nv_bfloat16 hz = __float2bfloat16(v.z), hw = __float2bfloat16(v.w);
            __nv_bfloat16 lx = __float2bfloat16(v.x - __bfloat162float(hx));
            __nv_bfloat16 ly = __float2bfloat16(v.y - __bfloat162float(hy));
            __nv_bfloat16 lz = __float2bfloat16(v.z - __bfloat162float(hz));
            __nv_bfloat16 lw = __float2bfloat16(v.w - __bfloat162float(hw));
            int o = row * PADK + k4;
            *(uint2*)&sAhi[o] = make_uint2(pk2(hx, hy), pk2(hz, hw));
            *(uint2*)&sAlo[o] = make_uint2(pk2(lx, ly), pk2(lz, lw));
        }
        // ---- B tile: 128 n-rows x 32 k of bf16 hi+lo ----
#pragma unroll
        for (int it = 0; it < 2; it++) {
            int f  = tid + it * 256;      // 0..511 uint4 slots (8 bf16 each)
            int n  = f >> 2;
            int k8 = (f & 3) * 8;
            int go = (n0 + n) * DD + kc + k8;
            int o  = n * PADK + k8;
            *(uint4*)&sBhi[o] = *(const uint4*)&g_Bhi[go];
            *(uint4*)&sBlo[o] = *(const uint4*)&g_Blo[go];
        }
        __syncthreads();

#pragma unroll
        for (int ks = 0; ks < BK; ks += 16) {
            uint32_t afh[2][4], afl[2][4], bfh[8][2], bfl[8][2];
#pragma unroll
            for (int mi = 0; mi < 2; mi++) {
                int r0 = (wm + mi * 16 + g) * PADK + ks + 2 * t;
                int r1 = r0 + 8 * PADK;
                afh[mi][0] = *(const uint32_t*)&sAhi[r0];
                afh[mi][1] = *(const uint32_t*)&sAhi[r1];
                afh[mi][2] = *(const uint32_t*)&sAhi[r0 + 8];
                afh[mi][3] = *(const uint32_t*)&sAhi[r1 + 8];
                afl[mi][0] = *(const uint32_t*)&sAlo[r0];
                afl[mi][1] = *(const uint32_t*)&sAlo[r1];
                afl[mi][2] = *(const uint32_t*)&sAlo[r0 + 8];
                afl[mi][3] = *(const uint32_t*)&sAlo[r1 + 8];
            }
#pragma unroll
            for (int ni = 0; ni < 8; ni++) {
                int o = (wn + ni * 8 + g) * PADK + ks + 2 * t;
                bfh[ni][0] = *(const uint32_t*)&sBhi[o];
                bfh[ni][1] = *(const uint32_t*)&sBhi[o + 8];
                bfl[ni][0] = *(const uint32_t*)&sBlo[o];
                bfl[ni][1] = *(const uint32_t*)&sBlo[o + 8];
            }
#pragma unroll
            for (int mi = 0; mi < 2; mi++)
#pragma unroll
                for (int ni = 0; ni < 8; ni++) {
                    mma16816(acc[mi][ni], afh[mi], bfh[ni]);
                    mma16816(acc[mi][ni], afh[mi], bfl[ni]);
                    mma16816(acc[mi][ni], afl[mi], bfh[ni]);
                }
        }
        __syncthreads();
    }

    // ---- epilogue: write S ----
#pragma unroll
    for (int mi = 0; mi < 2; mi++) {
        int r0 = m0 + wm + mi * 16 + g;
        int r1 = r0 + 8;
#pragma unroll
        for (int ni = 0; ni < 8; ni++) {
            int col = n0 + wn + ni * 8 + 2 * t;
            if (r0 < M)
                *(float2*)&S[(size_t)r0 * FF + col] = make_float2(acc[mi][ni][0], acc[mi][ni][1]);
            if (r1 < M)
                *(float2*)&S[(size_t)r1 * FF + col] = make_float2(acc[mi][ni][2], acc[mi][ni][3]);
        }
    }
}

// ---------------- CSR build ----------------
__global__ void zero_counts_kernel(int n)
{
    int i = blockIdx.x * blockDim.x + threadIdx.x;
    if (i <= n) g_counts[i] = 0;
}

__global__ void hist_kernel(const int* __restrict__ row, int E)
{
    int e = blockIdx.x * blockDim.x + threadIdx.x;
    if (e < E) atomicAdd(&g_counts[row[e]], 1);
}

__global__ __launch_bounds__(256)
void scan1_kernel(int n)
{
    __shared__ int ps[256];
    int b = blockIdx.x, t = threadIdx.x;
    int i0 = b * 512 + 2 * t;
    int c0 = (i0     < n) ? g_counts[i0]     : 0;
    int c1 = (i0 + 1 < n) ? g_counts[i0 + 1] : 0;
    ps[t] = c0 + c1;
    __syncthreads();
    for (int off = 1; off < 256; off <<= 1) {
        int v = (t >= off) ? ps[t - off] : 0;
        __syncthreads();
        ps[t] += v;
        __syncthreads();
    }
    int excl = ps[t] - (c0 + c1);
    if (i0     < n) g_offsets[i0]     = excl;
    if (i0 + 1 < n) g_offsets[i0 + 1] = excl + c0;
    if (t == 255) g_bsum[b] = ps[255];
}

__global__ void scan2_kernel(int nb, int n, int E)
{
    __shared__ int s[128];
    int t = threadIdx.x;
    int v = (t < nb) ? g_bsum[t] : 0;
    s[t] = v;
    __syncthreads();
    for (int off = 1; off < 128; off <<= 1) {
        int x = (t >= off) ? s[t - off] : 0;
        __syncthreads();
        s[t] += x;
        __syncthreads();
    }
    if (t < nb) g_bsum2[t] = s[t] - v;
    if (t == 0) g_offsets[n] = E;
}

__global__ void scan3_kernel(int n)
{
    int i = blockIdx.x * blockDim.x + threadIdx.x;
    if (i < n) {
        int v = g_offsets[i] + g_bsum2[i >> 9];
        g_offsets[i] = v;
        g_cursor[i]  = v;
    }
}

__global__ void scatter_kernel(const int* __restrict__ row, const int* __restrict__ col,
                               const float* __restrict__ val, int E)
{
    int e = blockIdx.x * blockDim.x + threadIdx.x;
    if (e < E) {
        int r = row[e];
        int p = atomicAdd(&g_cursor[r], 1);
        g_ecol[p] = col[e];
        g_eval[p] = val[e];
    }
}

// ---------------- aggregation (both branches) + bias + relu ----------------
__global__ __launch_bounds__(256)
void aggregate_kernel(const float* __restrict__ bias, float* __restrict__ out, int n)
{
    const int row = blockIdx.x;
    const int f   = threadIdx.x;

    const float* __restrict__ S0 = g_support;
    const float* __restrict__ S1 = g_support + (size_t)n * FF;
    int beg = g_offsets[row];
    int end = g_offsets[row + 1];

    __shared__ int   sc[64];
    __shared__ float sv[64];

    float a0 = 0.f, a1 = 0.f;
    for (int j0 = beg; j0 < end; j0 += 64) {
        int nb = end - j0;
        if (nb > 64) nb = 64;
        if (f < nb) {
            sc[f] = g_ecol[j0 + f] * FF;
            sv[f] = g_eval[j0 + f];
        }
        __syncthreads();
        for (int k = 0; k < nb; k++) {
            float wv = sv[k];
            size_t o = (size_t)sc[k] + f;
            a0 = fmaf(wv, S0[o], a0);
            a1 = fmaf(wv, S1[o], a1);
        }
        __syncthreads();
    }

    float bb = bias[f];
    out[(size_t)row * FF + f]       = fmaxf(a0 + bb, 0.f);
    out[((size_t)n + row) * FF + f] = fmaxf(a1 + bb, 0.f);
}

// ---------------- launch ----------------
extern "C" void kernel_launch(void* const* d_in, const int* in_sizes, int n_in,
                              void* d_out, int out_size)
{
    const float* feature_ori = (const float*)d_in[0];
    const float* feature_aug = (const float*)d_in[1];
    const int*   edge_row    = (const int*)d_in[2];
    const int*   edge_col    = (const int*)d_in[3];
    const float* edge_val    = (const float*)d_in[4];
    const float* bias        = (const float*)d_in[6];
    float*       out         = (float*)d_out;

    const int N = in_sizes[0] / DD;
    const int E = in_sizes[2];

    // W -> bf16 hi/lo transposed
    prep_w_kernel<<<(DD * FF + 255) / 256, 256>>>((const float*)d_in[5]);

    // support = X @ W, both branches (HMMA tensor cores)
    dim3 ggrid((N + BM - 1) / BM, FF / BN, 2);
    gemm_mma_kernel<<<ggrid, 256>>>(feature_ori, feature_aug, N);

    // CSR build
    zero_counts_kernel<<<(N + 256) / 256, 256>>>(N);
    hist_kernel<<<(E + 255) / 256, 256>>>(edge_row, E);
    int nb = (N + 511) / 512;
    scan1_kernel<<<nb, 256>>>(N);
    scan2_kernel<<<1, 128>>>(nb, N, E);
    scan3_kernel<<<(N + 255) / 256, 256>>>(N);
    scatter_kernel<<<(E + 255) / 256, 256>>>(edge_row, edge_col, edge_val, E);

    // aggregate + bias + relu
    aggregate_kernel<<<N, 256>>>(bias, out, N);
}

// round 4
// speedup vs baseline: 1.7518x; 1.1905x over previous
#include <cuda_runtime.h>
#include <cuda_bf16.h>
#include <cstdint>

#define NN 50000
#define EE 800000
#define DD 512
#define FF 256

// ---------------- device scratch ----------------
__device__ float         g_support[2 * (size_t)NN * FF];   // 102.4 MB
__device__ __nv_bfloat16 g_Bhi[FF * DD];                   // W^T hi, [256][512]
__device__ __nv_bfloat16 g_Blo[FF * DD];                   // W^T lo
__device__ int           g_counts[NN + 1];
__device__ int           g_offsets[NN + 1];
__device__ int           g_cursor[NN];
__device__ int           g_bsum[256];
__device__ int           g_bsum2[256];
__device__ int           g_ecol[EE];
__device__ float         g_eval[EE];

// ---------------- W prep: W[512][256] fp32 -> W^T hi/lo bf16 [256][512] ------
__global__ void prep_w_kernel(const float* __restrict__ W)
{
    int i = blockIdx.x * blockDim.x + threadIdx.x;
    if (i < DD * FF) {
        int k = i >> 8, n = i & 255;
        float w = W[i];
        __nv_bfloat16 h = __float2bfloat16(w);
        g_Bhi[n * DD + k] = h;
        g_Blo[n * DD + k] = __float2bfloat16(w - __bfloat162float(h));
    }
}

// ---------------- pipelined mma.sync bf16 GEMM (3-term hi/lo split) ----------
// S[b] = X_b @ W.  Block tile 64x256 (full FF), BK=32, 8 warps as 2m x 4n,
// warp tile 32x64.  2-stage cp.async pipeline, ldmatrix fragment loads.
#define BM 64
#define BN 256
#define BK 32
#define PADK 40          // k-stride in bf16 (80 B): ldmatrix conflict-free

#define OFF_AHI 0
#define OFF_ALO 5120
#define OFF_BHI 10240
#define OFF_BLO 30720
#define STAGE_BYTES 51200
#define SMEM_GEMM (2 * STAGE_BYTES)     // 102400

__device__ __forceinline__ uint32_t smem_u32(const void* p) {
    uint32_t a;
    asm("{ .reg .u64 t; cvta.to.shared.u64 t, %1; cvt.u32.u64 %0, t; }" : "=r"(a) : "l"(p));
    return a;
}
__device__ __forceinline__ void cp16(uint32_t saddr, const void* gaddr) {
    asm volatile("cp.async.cg.shared.global [%0], [%1], 16;" :: "r"(saddr), "l"(gaddr));
}
__device__ __forceinline__ void cp_commit() { asm volatile("cp.async.commit_group;"); }
__device__ __forceinline__ void cp_wait0()  { asm volatile("cp.async.wait_group 0;"); }

__device__ __forceinline__ void ldsm_x4(uint32_t* r, uint32_t addr) {
    asm volatile("ldmatrix.sync.aligned.m8n8.x4.shared.b16 {%0,%1,%2,%3}, [%4];"
                 : "=r"(r[0]), "=r"(r[1]), "=r"(r[2]), "=r"(r[3]) : "r"(addr));
}
__device__ __forceinline__ void mma16816(float* c, const uint32_t* a, const uint32_t* b)
{
    asm volatile(
        "mma.sync.aligned.m16n8k16.row.col.f32.bf16.bf16.f32 "
        "{%0,%1,%2,%3}, {%4,%5,%6,%7}, {%8,%9}, {%0,%1,%2,%3};"
        : "+f"(c[0]), "+f"(c[1]), "+f"(c[2]), "+f"(c[3])
        : "r"(a[0]), "r"(a[1]), "r"(a[2]), "r"(a[3]), "r"(b[0]), "r"(b[1]));
}
__device__ __forceinline__ uint32_t pk2(__nv_bfloat16 a, __nv_bfloat16 b) {
    __nv_bfloat162 t; t.x = a; t.y = b;
    return *reinterpret_cast<uint32_t*>(&t);
}

__global__ __launch_bounds__(256, 1)
void gemm_mma_kernel(const float* __restrict__ A0, const float* __restrict__ A1, int M)
{
    extern __shared__ char smem[];
    const uint32_t sb = smem_u32(smem);

    const int tid  = threadIdx.x;
    const int lane = tid & 31;
    const int w    = tid >> 5;
    const int wm   = (w >> 2) * 32;      // 0,32
    const int wn   = (w & 3) * 64;       // 0,64,128,192
    const int g    = lane >> 2;
    const int t    = lane & 3;

    const int m0 = blockIdx.x * BM;
    const float* __restrict__ A = blockIdx.z ? A1 : A0;
    float* __restrict__ S = g_support + (size_t)blockIdx.z * M * FF;

    // per-thread A slice: row = tid/4, 8 consecutive k at (tid%4)*8
    const int ar  = tid >> 2;
    const int ak8 = (tid & 3) * 8;
    const bool a_ok = (m0 + ar) < M;
    const float* aptr = A + (size_t)(m0 + ar) * DD + ak8;
    const uint32_t a_soff = (uint32_t)(ar * PADK + ak8) * 2;

    float4 va, vb;

    auto loadA = [&](int kc) {
        if (a_ok) {
            va = *(const float4*)(aptr + kc);
            vb = *(const float4*)(aptr + kc + 4);
        } else {
            va = make_float4(0.f, 0.f, 0.f, 0.f);
            vb = va;
        }
    };
    auto stA = [&](int stage) {
        float f[8] = {va.x, va.y, va.z, va.w, vb.x, vb.y, vb.z, vb.w};
        uint32_t hi[4], lo[4];
#pragma unroll
        for (int j = 0; j < 4; j++) {
            __nv_bfloat16 h0 = __float2bfloat16(f[2 * j]);
            __nv_bfloat16 h1 = __float2bfloat16(f[2 * j + 1]);
            __nv_bfloat16 l0 = __float2bfloat16(f[2 * j]     - __bfloat162float(h0));
            __nv_bfloat16 l1 = __float2bfloat16(f[2 * j + 1] - __bfloat162float(h1));
            hi[j] = pk2(h0, h1);
            lo[j] = pk2(l0, l1);
        }
        char* base = smem + stage * STAGE_BYTES;
        *(uint4*)(base + OFF_AHI + a_soff) = *(uint4*)hi;
        *(uint4*)(base + OFF_ALO + a_soff) = *(uint4*)lo;
    };
    auto cpB = [&](int kc, int stage) {
        uint32_t sbase = sb + stage * STAGE_BYTES;
#pragma unroll
        for (int it = 0; it < 4; it++) {
            int idx = tid + it * 256;            // 0..1023
            int n   = idx >> 2;
            int k8  = (idx & 3) * 8;
            uint32_t soff = (uint32_t)(n * PADK + k8) * 2;
            int goff = n * DD + kc + k8;
            cp16(sbase + OFF_BHI + soff, &g_Bhi[goff]);
            cp16(sbase + OFF_BLO + soff, &g_Blo[goff]);
        }
        cp_commit();
    };

    float acc[2][8][4];
#pragma unroll
    for (int mi = 0; mi < 2; mi++)
#pragma unroll
        for (int ni = 0; ni < 8; ni++)
#pragma unroll
            for (int j = 0; j < 4; j++) acc[mi][ni][j] = 0.f;

    // ldmatrix lane-address components
    const int a_row = wm + (lane & 15);              // + mi*16
    const int a_col = (lane >> 4) * 8;               // + ks
    const int b_nrو = 0;                              // (unused)
    const int b_n   = wn + (lane & 7) + ((lane >> 4) * 8);   // + p*16
    const int b_col = ((lane >> 3) & 1) * 8;                 // + ks

    // prologue
    loadA(0);
    cpB(0, 0);
    stA(0);
    cp_wait0();
    __syncthreads();

    for (int c = 0; c < DD / BK; c++) {
        const int cur = c & 1, nxt = cur ^ 1;
        const bool has = (c + 1) < DD / BK;
        if (has) {
            loadA((c + 1) * BK);
            cpB((c + 1) * BK, nxt);
        }

        const uint32_t abase = sb + cur * STAGE_BYTES;
#pragma unroll
        for (int ks = 0; ks < BK; ks += 16) {
            uint32_t afh[2][4], afl[2][4], bfh[4][4], bfl[4][4];
#pragma unroll
            for (int mi = 0; mi < 2; mi++) {
                uint32_t ao = (uint32_t)((a_row + mi * 16) * PADK + a_col + ks) * 2;
                ldsm_x4(afh[mi], abase + OFF_AHI + ao);
                ldsm_x4(afl[mi], abase + OFF_ALO + ao);
            }
#pragma unroll
            for (int p = 0; p < 4; p++) {
                uint32_t bo = (uint32_t)((b_n + p * 16) * PADK + b_col + ks) * 2;
                ldsm_x4(bfh[p], abase + OFF_BHI + bo);
                ldsm_x4(bfl[p], abase + OFF_BLO + bo);
            }
#pragma unroll
            for (int mi = 0; mi < 2; mi++)
#pragma unroll
                for (int ni = 0; ni < 8; ni++) {
                    const uint32_t* bh = &bfh[ni >> 1][(ni & 1) * 2];
                    const uint32_t* bl = &bfl[ni >> 1][(ni & 1) * 2];
                    mma16816(acc[mi][ni], afh[mi], bh);
                    mma16816(acc[mi][ni], afh[mi], bl);
                    mma16816(acc[mi][ni], afl[mi], bh);
                }
        }

        if (has) {
            stA(nxt);
            cp_wait0();
        }
        __syncthreads();
    }

    // epilogue
#pragma unroll
    for (int mi = 0; mi < 2; mi++) {
        int r0 = m0 + wm + mi * 16 + g;
        int r1 = r0 + 8;
#pragma unroll
        for (int ni = 0; ni < 8; ni++) {
            int col = wn + ni * 8 + 2 * t;
            if (r0 < M)
                *(float2*)&S[(size_t)r0 * FF + col] = make_float2(acc[mi][ni][0], acc[mi][ni][1]);
            if (r1 < M)
                *(float2*)&S[(size_t)r1 * FF + col] = make_float2(acc[mi][ni][2], acc[mi][ni][3]);
        }
    }
}

// ---------------- CSR build ----------------
__global__ void zero_counts_kernel(int n)
{
    int i = blockIdx.x * blockDim.x + threadIdx.x;
    if (i <= n) g_counts[i] = 0;
}

__global__ void hist_kernel(const int* __restrict__ row, int E)
{
    int e = blockIdx.x * blockDim.x + threadIdx.x;
    if (e < E) atomicAdd(&g_counts[row[e]], 1);
}

__global__ __launch_bounds__(256)
void scan1_kernel(int n)
{
    __shared__ int ps[256];
    int b = blockIdx.x, t = threadIdx.x;
    int i0 = b * 512 + 2 * t;
    int c0 = (i0     < n) ? g_counts[i0]     : 0;
    int c1 = (i0 + 1 < n) ? g_counts[i0 + 1] : 0;
    ps[t] = c0 + c1;
    __syncthreads();
    for (int off = 1; off < 256; off <<= 1) {
        int v = (t >= off) ? ps[t - off] : 0;
        __syncthreads();
        ps[t] += v;
        __syncthreads();
    }
    int excl = ps[t] - (c0 + c1);
    if (i0     < n) g_offsets[i0]     = excl;
    if (i0 + 1 < n) g_offsets[i0 + 1] = excl + c0;
    if (t == 255) g_bsum[b] = ps[255];
}

__global__ void scan2_kernel(int nb, int n, int E)
{
    __shared__ int s[128];
    int t = threadIdx.x;
    int v = (t < nb) ? g_bsum[t] : 0;
    s[t] = v;
    __syncthreads();
    for (int off = 1; off < 128; off <<= 1) {
        int x = (t >= off) ? s[t - off] : 0;
        __syncthreads();
        s[t] += x;
        __syncthreads();
    }
    if (t < nb) g_bsum2[t] = s[t] - v;
    if (t == 0) g_offsets[n] = E;
}

__global__ void scan3_kernel(int n)
{
    int i = blockIdx.x * blockDim.x + threadIdx.x;
    if (i < n) {
        int v = g_offsets[i] + g_bsum2[i >> 9];
        g_offsets[i] = v;
        g_cursor[i]  = v;
    }
}

__global__ void scatter_kernel(const int* __restrict__ row, const int* __restrict__ col,
                               const float* __restrict__ val, int E)
{
    int e = blockIdx.x * blockDim.x + threadIdx.x;
    if (e < E) {
        int r = row[e];
        int p = atomicAdd(&g_cursor[r], 1);
        g_ecol[p] = col[e];
        g_eval[p] = val[e];
    }
}

// ---------------- aggregation (both branches) + bias + relu ----------------
__global__ __launch_bounds__(256)
void aggregate_kernel(const float* __restrict__ bias, float* __restrict__ out, int n)
{
    const int row = blockIdx.x;
    const int f   = threadIdx.x;

    const float* __restrict__ S0 = g_support;
    const float* __restrict__ S1 = g_support + (size_t)n * FF;
    int beg = g_offsets[row];
    int end = g_offsets[row + 1];

    __shared__ int   sc[64];
    __shared__ float sv[64];

    float a0 = 0.f, a1 = 0.f;
    for (int j0 = beg; j0 < end; j0 += 64) {
        int nb = end - j0;
        if (nb > 64) nb = 64;
        if (f < nb) {
            sc[f] = g_ecol[j0 + f] * FF;
            sv[f] = g_eval[j0 + f];
        }
        __syncthreads();
        int k = 0;
        for (; k + 4 <= nb; k += 4) {
            float w0 = sv[k], w1 = sv[k + 1], w2 = sv[k + 2], w3 = sv[k + 3];
            int o0 = sc[k] + f, o1 = sc[k + 1] + f, o2 = sc[k + 2] + f, o3 = sc[k + 3] + f;
            float x0 = S0[o0], y0 = S1[o0];
            float x1 = S0[o1], y1 = S1[o1];
            float x2 = S0[o2], y2 = S1[o2];
            float x3 = S0[o3], y3 = S1[o3];
            a0 = fmaf(w0, x0, a0); a1 = fmaf(w0, y0, a1);
            a0 = fmaf(w1, x1, a0); a1 = fmaf(w1, y1, a1);
            a0 = fmaf(w2, x2, a0); a1 = fmaf(w2, y2, a1);
            a0 = fmaf(w3, x3, a0); a1 = fmaf(w3, y3, a1);
        }
        for (; k < nb; k++) {
            float wv = sv[k];
            int o = sc[k] + f;
            a0 = fmaf(wv, S0[o], a0);
            a1 = fmaf(wv, S1[o], a1);
        }
        __syncthreads();
    }

    float bb = bias[f];
    out[(size_t)row * FF + f]       = fmaxf(a0 + bb, 0.f);
    out[((size_t)n + row) * FF + f] = fmaxf(a1 + bb, 0.f);
}

// ---------------- launch ----------------
extern "C" void kernel_launch(void* const* d_in, const int* in_sizes, int n_in,
                              void* d_out, int out_size)
{
    const float* feature_ori = (const float*)d_in[0];
    const float* feature_aug = (const float*)d_in[1];
    const int*   edge_row    = (const int*)d_in[2];
    const int*   edge_col    = (const int*)d_in[3];
    const float* edge_val    = (const float*)d_in[4];
    const float* bias        = (const float*)d_in[6];
    float*       out         = (float*)d_out;

    const int N = in_sizes[0] / DD;
    const int E = in_sizes[2];

    cudaFuncSetAttribute(gemm_mma_kernel, cudaFuncAttributeMaxDynamicSharedMemorySize, SMEM_GEMM);

    // W -> bf16 hi/lo transposed
    prep_w_kernel<<<(DD * FF + 255) / 256, 256>>>((const float*)d_in[5]);

    // support = X @ W, both branches (pipelined HMMA)
    dim3 ggrid((N + BM - 1) / BM, 1, 2);
    gemm_mma_kernel<<<ggrid, 256, SMEM_GEMM>>>(feature_ori, feature_aug, N);

    // CSR build
    zero_counts_kernel<<<(N + 256) / 256, 256>>>(N);
    hist_kernel<<<(E + 255) / 256, 256>>>(edge_row, E);
    int nb = (N + 511) / 512;
    scan1_kernel<<<nb, 256>>>(N);
    scan2_kernel<<<1, 128>>>(nb, N, E);
    scan3_kernel<<<(N + 255) / 256, 256>>>(N);
    scatter_kernel<<<(E + 255) / 256, 256>>>(edge_row, edge_col, edge_val, E);

    // aggregate + bias + relu
    aggregate_kernel<<<N, 256>>>(bias, out, N);
}

// round 5
// speedup vs baseline: 2.1497x; 1.2271x over previous
#include <cuda_runtime.h>
#include <cuda_bf16.h>
#include <cuda_fp16.h>
#include <cstdint>

#define NN 50000
#define EE 800000
#define DD 512
#define FF 256

// ---------------- device scratch ----------------
__device__ __half        g_support_h[2 * (size_t)NN * FF];  // 51.2 MB (fp16)
__device__ __nv_bfloat16 g_Bhi[FF * DD];                    // W^T hi, [256][512]
__device__ __nv_bfloat16 g_Blo[FF * DD];                    // W^T lo
__device__ int           g_counts[NN + 1];
__device__ int           g_offsets[NN + 1];
__device__ int           g_cursor[NN];
__device__ int           g_bsum[256];
__device__ int           g_bsum2[256];
__device__ int           g_ecol[EE];
__device__ float         g_eval[EE];

// ---------------- W prep: W[512][256] fp32 -> W^T hi/lo bf16 [256][512] ------
__global__ void prep_w_kernel(const float* __restrict__ W)
{
    int i = blockIdx.x * blockDim.x + threadIdx.x;
    if (i < DD * FF) {
        int k = i >> 8, n = i & 255;
        float w = W[i];
        __nv_bfloat16 h = __float2bfloat16(w);
        g_Bhi[n * DD + k] = h;
        g_Blo[n * DD + k] = __float2bfloat16(w - __bfloat162float(h));
    }
}

// ---------------- pipelined mma.sync bf16 GEMM (3-term hi/lo split) ----------
#define BM 64
#define BN 256
#define BK 32
#define PADK 40

#define OFF_AHI 0
#define OFF_ALO 5120
#define OFF_BHI 10240
#define OFF_BLO 30720
#define STAGE_BYTES 51200
#define SMEM_GEMM (2 * STAGE_BYTES)

__device__ __forceinline__ uint32_t smem_u32(const void* p) {
    uint32_t a;
    asm("{ .reg .u64 t; cvta.to.shared.u64 t, %1; cvt.u32.u64 %0, t; }" : "=r"(a) : "l"(p));
    return a;
}
__device__ __forceinline__ void cp16(uint32_t saddr, const void* gaddr) {
    asm volatile("cp.async.cg.shared.global [%0], [%1], 16;" :: "r"(saddr), "l"(gaddr));
}
__device__ __forceinline__ void cp_commit() { asm volatile("cp.async.commit_group;"); }
__device__ __forceinline__ void cp_wait0()  { asm volatile("cp.async.wait_group 0;"); }

__device__ __forceinline__ void ldsm_x4(uint32_t* r, uint32_t addr) {
    asm volatile("ldmatrix.sync.aligned.m8n8.x4.shared.b16 {%0,%1,%2,%3}, [%4];"
                 : "=r"(r[0]), "=r"(r[1]), "=r"(r[2]), "=r"(r[3]) : "r"(addr));
}
__device__ __forceinline__ void mma16816(float* c, const uint32_t* a, const uint32_t* b)
{
    asm volatile(
        "mma.sync.aligned.m16n8k16.row.col.f32.bf16.bf16.f32 "
        "{%0,%1,%2,%3}, {%4,%5,%6,%7}, {%8,%9}, {%0,%1,%2,%3};"
        : "+f"(c[0]), "+f"(c[1]), "+f"(c[2]), "+f"(c[3])
        : "r"(a[0]), "r"(a[1]), "r"(a[2]), "r"(a[3]), "r"(b[0]), "r"(b[1]));
}
__device__ __forceinline__ uint32_t pk2(__nv_bfloat16 a, __nv_bfloat16 b) {
    __nv_bfloat162 t; t.x = a; t.y = b;
    return *reinterpret_cast<uint32_t*>(&t);
}

__global__ __launch_bounds__(256, 1)
void gemm_mma_kernel(const float* __restrict__ A0, const float* __restrict__ A1, int M)
{
    extern __shared__ char smem[];
    const uint32_t sb = smem_u32(smem);

    const int tid  = threadIdx.x;
    const int lane = tid & 31;
    const int w    = tid >> 5;
    const int wm   = (w >> 2) * 32;
    const int wn   = (w & 3) * 64;
    const int g    = lane >> 2;
    const int t    = lane & 3;

    const int m0 = blockIdx.x * BM;
    const float* __restrict__ A = blockIdx.z ? A1 : A0;
    __half* __restrict__ S = g_support_h + (size_t)blockIdx.z * M * FF;

    const int ar  = tid >> 2;
    const int ak8 = (tid & 3) * 8;
    const bool a_ok = (m0 + ar) < M;
    const float* aptr = A + (size_t)(m0 + ar) * DD + ak8;
    const uint32_t a_soff = (uint32_t)(ar * PADK + ak8) * 2;

    float4 va, vb;

    auto loadA = [&](int kc) {
        if (a_ok) {
            va = *(const float4*)(aptr + kc);
            vb = *(const float4*)(aptr + kc + 4);
        } else {
            va = make_float4(0.f, 0.f, 0.f, 0.f);
            vb = va;
        }
    };
    auto stA = [&](int stage) {
        float f[8] = {va.x, va.y, va.z, va.w, vb.x, vb.y, vb.z, vb.w};
        uint32_t hi[4], lo[4];
#pragma unroll
        for (int j = 0; j < 4; j++) {
            __nv_bfloat16 h0 = __float2bfloat16(f[2 * j]);
            __nv_bfloat16 h1 = __float2bfloat16(f[2 * j + 1]);
            __nv_bfloat16 l0 = __float2bfloat16(f[2 * j]     - __bfloat162float(h0));
            __nv_bfloat16 l1 = __float2bfloat16(f[2 * j + 1] - __bfloat162float(h1));
            hi[j] = pk2(h0, h1);
            lo[j] = pk2(l0, l1);
        }
        char* base = smem + stage * STAGE_BYTES;
        *(uint4*)(base + OFF_AHI + a_soff) = *(uint4*)hi;
        *(uint4*)(base + OFF_ALO + a_soff) = *(uint4*)lo;
    };
    auto cpB = [&](int kc, int stage) {
        uint32_t sbase = sb + stage * STAGE_BYTES;
#pragma unroll
        for (int it = 0; it < 4; it++) {
            int idx = tid + it * 256;
            int n   = idx >> 2;
            int k8  = (idx & 3) * 8;
            uint32_t soff = (uint32_t)(n * PADK + k8) * 2;
            int goff = n * DD + kc + k8;
            cp16(sbase + OFF_BHI + soff, &g_Bhi[goff]);
            cp16(sbase + OFF_BLO + soff, &g_Blo[goff]);
        }
        cp_commit();
    };

    float acc[2][8][4];
#pragma unroll
    for (int mi = 0; mi < 2; mi++)
#pragma unroll
        for (int ni = 0; ni < 8; ni++)
#pragma unroll
            for (int j = 0; j < 4; j++) acc[mi][ni][j] = 0.f;

    const int a_row = wm + (lane & 15);
    const int a_col = (lane >> 4) * 8;
    const int b_n   = wn + (lane & 7) + ((lane >> 4) * 8);
    const int b_col = ((lane >> 3) & 1) * 8;

    loadA(0);
    cpB(0, 0);
    stA(0);
    cp_wait0();
    __syncthreads();

    for (int c = 0; c < DD / BK; c++) {
        const int cur = c & 1, nxt = cur ^ 1;
        const bool has = (c + 1) < DD / BK;
        if (has) {
            loadA((c + 1) * BK);
            cpB((c + 1) * BK, nxt);
        }

        const uint32_t abase = sb + cur * STAGE_BYTES;
#pragma unroll
        for (int ks = 0; ks < BK; ks += 16) {
            uint32_t afh[2][4], afl[2][4], bfh[4][4], bfl[4][4];
#pragma unroll
            for (int mi = 0; mi < 2; mi++) {
                uint32_t ao = (uint32_t)((a_row + mi * 16) * PADK + a_col + ks) * 2;
                ldsm_x4(afh[mi], abase + OFF_AHI + ao);
                ldsm_x4(afl[mi], abase + OFF_ALO + ao);
            }
#pragma unroll
            for (int p = 0; p < 4; p++) {
                uint32_t bo = (uint32_t)((b_n + p * 16) * PADK + b_col + ks) * 2;
                ldsm_x4(bfh[p], abase + OFF_BHI + bo);
                ldsm_x4(bfl[p], abase + OFF_BLO + bo);
            }
#pragma unroll
            for (int mi = 0; mi < 2; mi++)
#pragma unroll
                for (int ni = 0; ni < 8; ni++) {
                    const uint32_t* bh = &bfh[ni >> 1][(ni & 1) * 2];
                    const uint32_t* bl = &bfl[ni >> 1][(ni & 1) * 2];
                    mma16816(acc[mi][ni], afh[mi], bh);
                    mma16816(acc[mi][ni], afh[mi], bl);
                    mma16816(acc[mi][ni], afl[mi], bh);
                }
        }

        if (has) {
            stA(nxt);
            cp_wait0();
        }
        __syncthreads();
    }

    // epilogue: fp32 acc -> fp16 support
#pragma unroll
    for (int mi = 0; mi < 2; mi++) {
        int r0 = m0 + wm + mi * 16 + g;
        int r1 = r0 + 8;
#pragma unroll
        for (int ni = 0; ni < 8; ni++) {
            int col = wn + ni * 8 + 2 * t;
            if (r0 < M)
                *(__half2*)&S[(size_t)r0 * FF + col] =
                    __floats2half2_rn(acc[mi][ni][0], acc[mi][ni][1]);
            if (r1 < M)
                *(__half2*)&S[(size_t)r1 * FF + col] =
                    __floats2half2_rn(acc[mi][ni][2], acc[mi][ni][3]);
        }
    }
}

// ---------------- CSR build ----------------
__global__ void zero_counts_kernel(int n)
{
    int i = blockIdx.x * blockDim.x + threadIdx.x;
    if (i <= n) g_counts[i] = 0;
}

__global__ void hist_kernel(const int* __restrict__ row, int E)
{
    int e = blockIdx.x * blockDim.x + threadIdx.x;
    if (e < E) atomicAdd(&g_counts[row[e]], 1);
}

__global__ __launch_bounds__(256)
void scan1_kernel(int n)
{
    __shared__ int ps[256];
    int b = blockIdx.x, t = threadIdx.x;
    int i0 = b * 512 + 2 * t;
    int c0 = (i0     < n) ? g_counts[i0]     : 0;
    int c1 = (i0 + 1 < n) ? g_counts[i0 + 1] : 0;
    ps[t] = c0 + c1;
    __syncthreads();
    for (int off = 1; off < 256; off <<= 1) {
        int v = (t >= off) ? ps[t - off] : 0;
        __syncthreads();
        ps[t] += v;
        __syncthreads();
    }
    int excl = ps[t] - (c0 + c1);
    if (i0     < n) g_offsets[i0]     = excl;
    if (i0 + 1 < n) g_offsets[i0 + 1] = excl + c0;
    if (t == 255) g_bsum[b] = ps[255];
}

__global__ void scan2_kernel(int nb, int n, int E)
{
    __shared__ int s[128];
    int t = threadIdx.x;
    int v = (t < nb) ? g_bsum[t] : 0;
    s[t] = v;
    __syncthreads();
    for (int off = 1; off < 128; off <<= 1) {
        int x = (t >= off) ? s[t - off] : 0;
        __syncthreads();
        s[t] += x;
        __syncthreads();
    }
    if (t < nb) g_bsum2[t] = s[t] - v;
    if (t == 0) g_offsets[n] = E;
}

__global__ void scan3_kernel(int n)
{
    int i = blockIdx.x * blockDim.x + threadIdx.x;
    if (i < n) {
        int v = g_offsets[i] + g_bsum2[i >> 9];
        g_offsets[i] = v;
        g_cursor[i]  = v;
    }
}

__global__ void scatter_kernel(const int* __restrict__ row, const int* __restrict__ col,
                               const float* __restrict__ val, int E)
{
    int e = blockIdx.x * blockDim.x + threadIdx.x;
    if (e < E) {
        int r = row[e];
        int p = atomicAdd(&g_cursor[r], 1);
        g_ecol[p] = col[e];
        g_eval[p] = val[e];
    }
}

// ---------------- aggregation (both branches, fp16 support) ------------------
// 128 threads per row; thread t owns features {2t, 2t+1} via __half2.
__global__ __launch_bounds__(128)
void aggregate_kernel(const float* __restrict__ bias, float* __restrict__ out, int n)
{
    const int row = blockIdx.x;
    const int t   = threadIdx.x;

    const __half2* __restrict__ S0 = (const __half2*)g_support_h;
    const __half2* __restrict__ S1 = S0 + (size_t)n * (FF / 2);
    int beg = g_offsets[row];
    int end = g_offsets[row + 1];

    __shared__ int   sc[64];
    __shared__ float sv[64];

    float a00 = 0.f, a01 = 0.f, a10 = 0.f, a11 = 0.f;
    for (int j0 = beg; j0 < end; j0 += 64) {
        int nb = end - j0;
        if (nb > 64) nb = 64;
        if (t < nb) {
            sc[t] = g_ecol[j0 + t] * (FF / 2);
            sv[t] = g_eval[j0 + t];
        }
        __syncthreads();
        int k = 0;
        for (; k + 2 <= nb; k += 2) {
            float w0 = sv[k], w1 = sv[k + 1];
            int o0 = sc[k] + t, o1 = sc[k + 1] + t;
            __half2 x0 = S0[o0], y0 = S1[o0];
            __half2 x1 = S0[o1], y1 = S1[o1];
            float2 xf0 = __half22float2(x0), yf0 = __half22float2(y0);
            float2 xf1 = __half22float2(x1), yf1 = __half22float2(y1);
            a00 = fmaf(w0, xf0.x, a00); a01 = fmaf(w0, xf0.y, a01);
            a10 = fmaf(w0, yf0.x, a10); a11 = fmaf(w0, yf0.y, a11);
            a00 = fmaf(w1, xf1.x, a00); a01 = fmaf(w1, xf1.y, a01);
            a10 = fmaf(w1, yf1.x, a10); a11 = fmaf(w1, yf1.y, a11);
        }
        for (; k < nb; k++) {
            float wv = sv[k];
            int o = sc[k] + t;
            float2 xf = __half22float2(S0[o]);
            float2 yf = __half22float2(S1[o]);
            a00 = fmaf(wv, xf.x, a00); a01 = fmaf(wv, xf.y, a01);
            a10 = fmaf(wv, yf.x, a10); a11 = fmaf(wv, yf.y, a11);
        }
        __syncthreads();
    }

    float b0 = bias[2 * t], b1 = bias[2 * t + 1];
    *(float2*)&out[(size_t)row * FF + 2 * t] =
        make_float2(fmaxf(a00 + b0, 0.f), fmaxf(a01 + b1, 0.f));
    *(float2*)&out[((size_t)n + row) * FF + 2 * t] =
        make_float2(fmaxf(a10 + b0, 0.f), fmaxf(a11 + b1, 0.f));
}

// ---------------- launch ----------------
extern "C" void kernel_launch(void* const* d_in, const int* in_sizes, int n_in,
                              void* d_out, int out_size)
{
    const float* feature_ori = (const float*)d_in[0];
    const float* feature_aug = (const float*)d_in[1];
    const int*   edge_row    = (const int*)d_in[2];
    const int*   edge_col    = (const int*)d_in[3];
    const float* edge_val    = (const float*)d_in[4];
    const float* bias        = (const float*)d_in[6];
    float*       out         = (float*)d_out;

    const int N = in_sizes[0] / DD;
    const int E = in_sizes[2];

    cudaFuncSetAttribute(gemm_mma_kernel, cudaFuncAttributeMaxDynamicSharedMemorySize, SMEM_GEMM);

    prep_w_kernel<<<(DD * FF + 255) / 256, 256>>>((const float*)d_in[5]);

    dim3 ggrid((N + BM - 1) / BM, 1, 2);
    gemm_mma_kernel<<<ggrid, 256, SMEM_GEMM>>>(feature_ori, feature_aug, N);

    zero_counts_kernel<<<(N + 256) / 256, 256>>>(N);
    hist_kernel<<<(E + 255) / 256, 256>>>(edge_row, E);
    int nb = (N + 511) / 512;
    scan1_kernel<<<nb, 256>>>(N);
    scan2_kernel<<<1, 128>>>(nb, N, E);
    scan3_kernel<<<(N + 255) / 256, 256>>>(N);
    scatter_kernel<<<(E + 255) / 256, 256>>>(edge_row, edge_col, edge_val, E);

    aggregate_kernel<<<N, 128>>>(bias, out, N);
}

// round 6
// speedup vs baseline: 2.3275x; 1.0827x over previous
#include <cuda_runtime.h>
#include <cuda_bf16.h>
#include <cuda_fp16.h>
#include <cstdint>

#define NN 50000
#define EE 800000
#define DD 512
#define FF 256

// ---------------- device scratch ----------------
__device__ __half        g_support_h[2 * (size_t)NN * FF];  // 51.2 MB (fp16)
__device__ __nv_bfloat16 g_Bhi[FF * DD];                    // W^T hi, [256][512]
__device__ __nv_bfloat16 g_Blo[FF * DD];                    // W^T lo
__device__ int           g_counts[NN + 1];
__device__ int           g_offsets[NN + 1];
__device__ int           g_cursor[NN];
__device__ int           g_bsum[256];
__device__ int           g_bsum2[256];
__device__ int           g_ecol[EE];
__device__ float         g_eval[EE];

// ---------------- W prep ----------------
__global__ void prep_w_kernel(const float* __restrict__ W)
{
    int i = blockIdx.x * blockDim.x + threadIdx.x;
    if (i < DD * FF) {
        int k = i >> 8, n = i & 255;
        float w = W[i];
        __nv_bfloat16 h = __float2bfloat16(w);
        g_Bhi[n * DD + k] = h;
        g_Blo[n * DD + k] = __float2bfloat16(w - __bfloat162float(h));
    }
}

// ---------------- pipelined mma.sync bf16 GEMM (3-term hi/lo split) ----------
// Block tile 128x256, BK=32, 8 warps as 2m x 4n, warp tile 64x64.
#define BM 128
#define BN 256
#define BK 32
#define PADK 40

#define OFF_AHI 0
#define OFF_ALO 10240
#define OFF_BHI 20480
#define OFF_BLO 40960
#define STAGE_BYTES 61440
#define SMEM_GEMM (2 * STAGE_BYTES)     // 122880

__device__ __forceinline__ uint32_t smem_u32(const void* p) {
    uint32_t a;
    asm("{ .reg .u64 t; cvta.to.shared.u64 t, %1; cvt.u32.u64 %0, t; }" : "=r"(a) : "l"(p));
    return a;
}
__device__ __forceinline__ void cp16(uint32_t saddr, const void* gaddr) {
    asm volatile("cp.async.cg.shared.global [%0], [%1], 16;" :: "r"(saddr), "l"(gaddr));
}
__device__ __forceinline__ void cp_commit() { asm volatile("cp.async.commit_group;"); }
__device__ __forceinline__ void cp_wait0()  { asm volatile("cp.async.wait_group 0;"); }

__device__ __forceinline__ void ldsm_x4(uint32_t* r, uint32_t addr) {
    asm volatile("ldmatrix.sync.aligned.m8n8.x4.shared.b16 {%0,%1,%2,%3}, [%4];"
                 : "=r"(r[0]), "=r"(r[1]), "=r"(r[2]), "=r"(r[3]) : "r"(addr));
}
__device__ __forceinline__ void mma16816(float* c, const uint32_t* a, const uint32_t* b)
{
    asm volatile(
        "mma.sync.aligned.m16n8k16.row.col.f32.bf16.bf16.f32 "
        "{%0,%1,%2,%3}, {%4,%5,%6,%7}, {%8,%9}, {%0,%1,%2,%3};"
        : "+f"(c[0]), "+f"(c[1]), "+f"(c[2]), "+f"(c[3])
        : "r"(a[0]), "r"(a[1]), "r"(a[2]), "r"(a[3]), "r"(b[0]), "r"(b[1]));
}
__device__ __forceinline__ uint32_t pk2(__nv_bfloat16 a, __nv_bfloat16 b) {
    __nv_bfloat162 t; t.x = a; t.y = b;
    return *reinterpret_cast<uint32_t*>(&t);
}

__global__ __launch_bounds__(256, 1)
void gemm_mma_kernel(const float* __restrict__ A0, const float* __restrict__ A1, int M)
{
    extern __shared__ char smem[];
    const uint32_t sb = smem_u32(smem);

    const int tid  = threadIdx.x;
    const int lane = tid & 31;
    const int w    = tid >> 5;
    const int wm   = (w >> 2) * 64;      // 0,64
    const int wn   = (w & 3) * 64;       // 0,64,128,192
    const int g    = lane >> 2;
    const int t    = lane & 3;

    const int m0 = blockIdx.x * BM;
    const float* __restrict__ A = blockIdx.z ? A1 : A0;
    __half* __restrict__ S = g_support_h + (size_t)blockIdx.z * M * FF;

    // per-thread A slice: row = tid/2, 16 consecutive k at (tid%2)*16
    const int ar   = tid >> 1;
    const int ak16 = (tid & 1) * 16;
    const bool a_ok = (m0 + ar) < M;
    const float* aptr = A + (size_t)(m0 + ar) * DD + ak16;
    const uint32_t a_soff = (uint32_t)(ar * PADK + ak16) * 2;

    float4 v0, v1, v2, v3;

    auto loadA = [&](int kc) {
        if (a_ok) {
            v0 = *(const float4*)(aptr + kc);
            v1 = *(const float4*)(aptr + kc + 4);
            v2 = *(const float4*)(aptr + kc + 8);
            v3 = *(const float4*)(aptr + kc + 12);
        } else {
            v0 = make_float4(0.f, 0.f, 0.f, 0.f);
            v1 = v0; v2 = v0; v3 = v0;
        }
    };
    auto stA = [&](int stage) {
        float f[16] = {v0.x, v0.y, v0.z, v0.w, v1.x, v1.y, v1.z, v1.w,
                       v2.x, v2.y, v2.z, v2.w, v3.x, v3.y, v3.z, v3.w};
        uint32_t hi[8], lo[8];
#pragma unroll
        for (int j = 0; j < 8; j++) {
            __nv_bfloat16 h0 = __float2bfloat16(f[2 * j]);
            __nv_bfloat16 h1 = __float2bfloat16(f[2 * j + 1]);
            __nv_bfloat16 l0 = __float2bfloat16(f[2 * j]     - __bfloat162float(h0));
            __nv_bfloat16 l1 = __float2bfloat16(f[2 * j + 1] - __bfloat162float(h1));
            hi[j] = pk2(h0, h1);
            lo[j] = pk2(l0, l1);
        }
        char* base = smem + stage * STAGE_BYTES;
        *(uint4*)(base + OFF_AHI + a_soff)      = *(uint4*)&hi[0];
        *(uint4*)(base + OFF_AHI + a_soff + 16) = *(uint4*)&hi[4];
        *(uint4*)(base + OFF_ALO + a_soff)      = *(uint4*)&lo[0];
        *(uint4*)(base + OFF_ALO + a_soff + 16) = *(uint4*)&lo[4];
    };
    auto cpB = [&](int kc, int stage) {
        uint32_t sbase = sb + stage * STAGE_BYTES;
#pragma unroll
        for (int it = 0; it < 4; it++) {
            int idx = tid + it * 256;            // 0..1023
            int n   = idx >> 2;
            int k8  = (idx & 3) * 8;
            uint32_t soff = (uint32_t)(n * PADK + k8) * 2;
            int goff = n * DD + kc + k8;
            cp16(sbase + OFF_BHI + soff, &g_Bhi[goff]);
            cp16(sbase + OFF_BLO + soff, &g_Blo[goff]);
        }
        cp_commit();
    };

    float acc[4][8][4];
#pragma unroll
    for (int mi = 0; mi < 4; mi++)
#pragma unroll
        for (int ni = 0; ni < 8; ni++)
#pragma unroll
            for (int j = 0; j < 4; j++) acc[mi][ni][j] = 0.f;

    const int a_row = wm + (lane & 15);
    const int a_col = (lane >> 4) * 8;
    const int b_n   = wn + (lane & 7) + ((lane >> 4) * 8);
    const int b_col = ((lane >> 3) & 1) * 8;

    loadA(0);
    cpB(0, 0);
    stA(0);
    cp_wait0();
    __syncthreads();

    for (int c = 0; c < DD / BK; c++) {
        const int cur = c & 1, nxt = cur ^ 1;
        const bool has = (c + 1) < DD / BK;
        if (has) {
            loadA((c + 1) * BK);
            cpB((c + 1) * BK, nxt);
        }

        const uint32_t abase = sb + cur * STAGE_BYTES;
#pragma unroll
        for (int ks = 0; ks < BK; ks += 16) {
            uint32_t afh[4][4], afl[4][4], bfh[4][4], bfl[4][4];
#pragma unroll
            for (int mi = 0; mi < 4; mi++) {
                uint32_t ao = (uint32_t)((a_row + mi * 16) * PADK + a_col + ks) * 2;
                ldsm_x4(afh[mi], abase + OFF_AHI + ao);
                ldsm_x4(afl[mi], abase + OFF_ALO + ao);
            }
#pragma unroll
            for (int p = 0; p < 4; p++) {
                uint32_t bo = (uint32_t)((b_n + p * 16) * PADK + b_col + ks) * 2;
                ldsm_x4(bfh[p], abase + OFF_BHI + bo);
                ldsm_x4(bfl[p], abase + OFF_BLO + bo);
            }
#pragma unroll
            for (int mi = 0; mi < 4; mi++)
#pragma unroll
                for (int ni = 0; ni < 8; ni++) {
                    const uint32_t* bh = &bfh[ni >> 1][(ni & 1) * 2];
                    const uint32_t* bl = &bfl[ni >> 1][(ni & 1) * 2];
                    mma16816(acc[mi][ni], afh[mi], bh);
                    mma16816(acc[mi][ni], afh[mi], bl);
                    mma16816(acc[mi][ni], afl[mi], bh);
                }
        }

        if (has) {
            stA(nxt);
            cp_wait0();
        }
        __syncthreads();
    }

    // epilogue: fp32 acc -> fp16 support
#pragma unroll
    for (int mi = 0; mi < 4; mi++) {
        int r0 = m0 + wm + mi * 16 + g;
        int r1 = r0 + 8;
#pragma unroll
        for (int ni = 0; ni < 8; ni++) {
            int col = wn + ni * 8 + 2 * t;
            if (r0 < M)
                *(__half2*)&S[(size_t)r0 * FF + col] =
                    __floats2half2_rn(acc[mi][ni][0], acc[mi][ni][1]);
            if (r1 < M)
                *(__half2*)&S[(size_t)r1 * FF + col] =
                    __floats2half2_rn(acc[mi][ni][2], acc[mi][ni][3]);
        }
    }
}

// ---------------- CSR build ----------------
__global__ void zero_counts_kernel(int n)
{
    int i = blockIdx.x * blockDim.x + threadIdx.x;
    if (i <= n) g_counts[i] = 0;
}

__global__ void hist_kernel(const int* __restrict__ row, int E)
{
    int e = blockIdx.x * blockDim.x + threadIdx.x;
    if (e < E) atomicAdd(&g_counts[row[e]], 1);
}

__global__ __launch_bounds__(256)
void scan1_kernel(int n)
{
    __shared__ int ps[256];
    int b = blockIdx.x, t = threadIdx.x;
    int i0 = b * 512 + 2 * t;
    int c0 = (i0     < n) ? g_counts[i0]     : 0;
    int c1 = (i0 + 1 < n) ? g_counts[i0 + 1] : 0;
    ps[t] = c0 + c1;
    __syncthreads();
    for (int off = 1; off < 256; off <<= 1) {
        int v = (t >= off) ? ps[t - off] : 0;
        __syncthreads();
        ps[t] += v;
        __syncthreads();
    }
    int excl = ps[t] - (c0 + c1);
    if (i0     < n) g_offsets[i0]     = excl;
    if (i0 + 1 < n) g_offsets[i0 + 1] = excl + c0;
    if (t == 255) g_bsum[b] = ps[255];
}

__global__ void scan2_kernel(int nb, int n, int E)
{
    __shared__ int s[128];
    int t = threadIdx.x;
    int v = (t < nb) ? g_bsum[t] : 0;
    s[t] = v;
    __syncthreads();
    for (int off = 1; off < 128; off <<= 1) {
        int x = (t >= off) ? s[t - off] : 0;
        __syncthreads();
        s[t] += x;
        __syncthreads();
    }
    if (t < nb) g_bsum2[t] = s[t] - v;
    if (t == 0) g_offsets[n] = E;
}

__global__ void scan3_kernel(int n)
{
    int i = blockIdx.x * blockDim.x + threadIdx.x;
    if (i < n) {
        int v = g_offsets[i] + g_bsum2[i >> 9];
        g_offsets[i] = v;
        g_cursor[i]  = v;
    }
}

__global__ void scatter_kernel(const int* __restrict__ row, const int* __restrict__ col,
                               const float* __restrict__ val, int E)
{
    int e = blockIdx.x * blockDim.x + threadIdx.x;
    if (e < E) {
        int r = row[e];
        int p = atomicAdd(&g_cursor[r], 1);
        g_ecol[p] = col[e];
        g_eval[p] = val[e];
    }
}

// ---------------- aggregation (both branches, fp16 support) ------------------
__global__ __launch_bounds__(128)
void aggregate_kernel(const float* __restrict__ bias, float* __restrict__ out, int n)
{
    const int row = blockIdx.x;
    const int t   = threadIdx.x;

    const __half2* __restrict__ S0 = (const __half2*)g_support_h;
    const __half2* __restrict__ S1 = S0 + (size_t)n * (FF / 2);
    int beg = g_offsets[row];
    int end = g_offsets[row + 1];

    __shared__ int   sc[64];
    __shared__ float sv[64];

    float a00 = 0.f, a01 = 0.f, a10 = 0.f, a11 = 0.f;
    for (int j0 = beg; j0 < end; j0 += 64) {
        int nb = end - j0;
        if (nb > 64) nb = 64;
        if (t < nb) {
            sc[t] = g_ecol[j0 + t] * (FF / 2);
            sv[t] = g_eval[j0 + t];
        }
        __syncthreads();
        int k = 0;
        for (; k + 2 <= nb; k += 2) {
            float w0 = sv[k], w1 = sv[k + 1];
            int o0 = sc[k] + t, o1 = sc[k + 1] + t;
            __half2 x0 = S0[o0], y0 = S1[o0];
            __half2 x1 = S0[o1], y1 = S1[o1];
            float2 xf0 = __half22float2(x0), yf0 = __half22float2(y0);
            float2 xf1 = __half22float2(x1), yf1 = __half22float2(y1);
            a00 = fmaf(w0, xf0.x, a00); a01 = fmaf(w0, xf0.y, a01);
            a10 = fmaf(w0, yf0.x, a10); a11 = fmaf(w0, yf0.y, a11);
            a00 = fmaf(w1, xf1.x, a00); a01 = fmaf(w1, xf1.y, a01);
            a10 = fmaf(w1, yf1.x, a10); a11 = fmaf(w1, yf1.y, a11);
        }
        for (; k < nb; k++) {
            float wv = sv[k];
            int o = sc[k] + t;
            float2 xf = __half22float2(S0[o]);
            float2 yf = __half22float2(S1[o]);
            a00 = fmaf(wv, xf.x, a00); a01 = fmaf(wv, xf.y, a01);
            a10 = fmaf(wv, yf.x, a10); a11 = fmaf(wv, yf.y, a11);
        }
        __syncthreads();
    }

    float b0 = bias[2 * t], b1 = bias[2 * t + 1];
    *(float2*)&out[(size_t)row * FF + 2 * t] =
        make_float2(fmaxf(a00 + b0, 0.f), fmaxf(a01 + b1, 0.f));
    *(float2*)&out[((size_t)n + row) * FF + 2 * t] =
        make_float2(fmaxf(a10 + b0, 0.f), fmaxf(a11 + b1, 0.f));
}

// ---------------- launch ----------------
extern "C" void kernel_launch(void* const* d_in, const int* in_sizes, int n_in,
                              void* d_out, int out_size)
{
    const float* feature_ori = (const float*)d_in[0];
    const float* feature_aug = (const float*)d_in[1];
    const int*   edge_row    = (const int*)d_in[2];
    const int*   edge_col    = (const int*)d_in[3];
    const float* edge_val    = (const float*)d_in[4];
    const float* bias        = (const float*)d_in[6];
    float*       out         = (float*)d_out;

    const int N = in_sizes[0] / DD;
    const int E = in_sizes[2];

    cudaFuncSetAttribute(gemm_mma_kernel, cudaFuncAttributeMaxDynamicSharedMemorySize, SMEM_GEMM);

    // launch order puts gemm 4th so ncu's fixed slot profiles it
    prep_w_kernel<<<(DD * FF + 255) / 256, 256>>>((const float*)d_in[5]);
    zero_counts_kernel<<<(N + 256) / 256, 256>>>(N);
    hist_kernel<<<(E + 255) / 256, 256>>>(edge_row, E);

    dim3 ggrid((N + BM - 1) / BM, 1, 2);
    gemm_mma_kernel<<<ggrid, 256, SMEM_GEMM>>>(feature_ori, feature_aug, N);

    int nb = (N + 511) / 512;
    scan1_kernel<<<nb, 256>>>(N);
    scan2_kernel<<<1, 128>>>(nb, N, E);
    scan3_kernel<<<(N + 255) / 256, 256>>>(N);
    scatter_kernel<<<(E + 255) / 256, 256>>>(edge_row, edge_col, edge_val, E);

    aggregate_kernel<<<N, 128>>>(bias, out, N);
}